// round 11
// baseline (speedup 1.0000x reference)
#include <cuda_runtime.h>
#include <cuda_bf16.h>
#include <math.h>
#include <stdint.h>

// Shapes: x[8,128,64,64] off_w[27,128,3,3] off_b[27] w[128,128,3,3] b[128]
//         gamma[128] beta[128] -> out[8,128,64,64] fp32

#define NB   8
#define NC   128
#define NH   64
#define NW   64
#define NHW  4096
#define NKT  9
#define NOFF 27
#define KDIM 1152   // 128*9

static __device__ float    g_om[NB * NOFF * NHW];  // offset-conv output
static __device__ uint32_t g_w2[NC * KDIM];        // w permuted [o][kt*128+ci], tf32 bits
static __device__ float    g_xT[NB * NHW * NC];    // x transposed to NHWC
static __device__ float    g_y[NB * NC * NHW];     // pre-BN conv output
static __device__ float    g_stats[2 * NC];        // per-channel sum, sumsq

// ---------------- helpers ---------------------------------------------------
__device__ __forceinline__ uint32_t f2tf32(float v) {
    uint32_t r;
    asm("cvt.rna.tf32.f32 %0, %1;" : "=r"(r) : "f"(v));
    return r;
}
__device__ __forceinline__ void mma_tf32(float4& d, const uint32_t a[4],
                                         const uint32_t b[2]) {
    asm volatile(
        "mma.sync.aligned.m16n8k8.row.col.f32.tf32.tf32.f32 "
        "{%0,%1,%2,%3}, {%4,%5,%6,%7}, {%8,%9}, {%0,%1,%2,%3};"
        : "+f"(d.x), "+f"(d.y), "+f"(d.z), "+f"(d.w)
        : "r"(a[0]), "r"(a[1]), "r"(a[2]), "r"(a[3]), "r"(b[0]), "r"(b[1]));
}
__device__ __forceinline__ void ffma2(unsigned long long& d,
                                      unsigned long long a,
                                      unsigned long long b) {
    asm volatile("fma.rn.f32x2 %0, %1, %2, %0;" : "+l"(d) : "l"(a), "l"(b));
}
__device__ __forceinline__ unsigned long long pack2(float lo, float hi) {
    unsigned long long r;
    asm("mov.b64 %0, {%1, %2};" : "=l"(r) : "f"(lo), "f"(hi));
    return r;
}
__device__ __forceinline__ float2 unpack2(unsigned long long v) {
    float2 r;
    asm("mov.b64 {%0, %1}, %2;" : "=f"(r.x), "=f"(r.y) : "l"(v));
    return r;
}

// SMEM layout (byte offsets), tiles stride 36 floats. M-tile = 64 px.
#define OFF_SUM  0         // 512
#define OFF_SSQ  512       // 512
#define OFF_BIAS 1024      // 512
#define OFF_CO   1536      // 9*64*8  = 4608 (ushort4 corner plane-indices)
#define OFF_WQ   6144      // 9*64*16 = 9216 (float4 bilinear weights)
#define OFF_A0   15360     // 64*36*4 = 9216
#define OFF_A1   24576
#define OFF_W0   33792     // 128*36*4 = 18432
#define OFF_W1   52224
#define SMEM_SZ  70656
#define TSTRIDE  36

// ---------------------------------------------------------------------------
// Kernel Z: zero stats + permute weights to [o][kt*128+ci], tf32 bits
// ---------------------------------------------------------------------------
__global__ void prep_kernel(const float* __restrict__ w) {
    if (blockIdx.x == 0 && threadIdx.x < 2 * NC) g_stats[threadIdx.x] = 0.0f;
    int n = NC * KDIM;
    for (int i = blockIdx.x * blockDim.x + threadIdx.x; i < n;
         i += gridDim.x * blockDim.x) {
        int o  = i / KDIM;
        int r  = i - o * KDIM;
        int kt = r >> 7;
        int ci = r & 127;
        g_w2[i] = f2tf32(w[o * KDIM + ci * 9 + kt]);
    }
}

// ---------------------------------------------------------------------------
// Kernel T: NCHW -> NHWC transpose of x (SMEM-tiled, coalesced both sides)
// grid (8, 64, 8): bx = {ciTile 0..3} x {wTile 0..1}, by = h, bz = b
// ---------------------------------------------------------------------------
__global__ __launch_bounds__(256) void transpose_kernel(
    const float* __restrict__ x) {
    __shared__ float t[32][33];
    const int tid  = threadIdx.x;
    const int lane = tid & 31;
    const int row  = tid >> 5;         // 0..7
    const int bX   = blockIdx.x;
    const int ciT  = bX >> 1;          // 0..3
    const int wT   = bX & 1;           // 0..1
    const int h    = blockIdx.y;
    const int b    = blockIdx.z;

#pragma unroll
    for (int i = 0; i < 4; ++i) {
        int ci = ciT * 32 + row + i * 8;
        int w  = wT * 32 + lane;
        t[row + i * 8][lane] =
            __ldg(x + ((size_t)(b * NC + ci) << 12) + (h << 6) + w);
    }
    __syncthreads();
#pragma unroll
    for (int i = 0; i < 4; ++i) {
        int w  = wT * 32 + row + i * 8;
        int ci = ciT * 32 + lane;
        g_xT[(((size_t)(b << 12)) + (h << 6) + w) * NC + ci] =
            t[lane][row + i * 8];
    }
}

// ---------------------------------------------------------------------------
// Kernel A: offset conv (NCHW x). 256 blocks, 4 channels / iteration.
// ---------------------------------------------------------------------------
__global__ __launch_bounds__(256) void off_conv_kernel(
    const float* __restrict__ x,
    const float* __restrict__ ow,
    const float* __restrict__ ob) {
    __shared__ float xt[4][10][18];
    __shared__ unsigned long long wdup[4 * 243];

    const int tid  = threadIdx.x;
    const int og   = tid >> 6;
    const int slot = tid & 63;
    const int lr   = slot >> 4;
    const int lc   = slot & 15;
    const int b    = blockIdx.z;
    const int by   = blockIdx.y;
    const int bx   = blockIdx.x;

    unsigned long long accp[7];
#pragma unroll
    for (int j = 0; j < 7; ++j) accp[j] = 0ull;

    for (int it = 0; it < 32; ++it) {
        const int ci0 = it << 2;
        __syncthreads();
        for (int i = tid; i < 720; i += 256) {
            int ci  = i / 180;
            int rem = i - ci * 180;
            int r   = rem / 18;
            int cp  = rem - r * 18;
            int gy  = by * 8 + r - 1;
            int gx  = bx * 16 + cp - 1;
            float v = 0.0f;
            if (gy >= 0 && gy < NH && gx >= 0 && gx < NW)
                v = __ldg(x + ((size_t)(b * NC + ci0 + ci) << 12) + (gy << 6) + gx);
            xt[ci][r][cp] = v;
        }
        for (int i = tid; i < 972; i += 256) {
            int ci  = i / 243;
            int rem = i - ci * 243;
            int o   = rem / 9;
            int t   = rem - o * 9;
            float wv = __ldg(ow + (size_t)o * KDIM + (ci0 + ci) * 9 + t);
            wdup[i] = pack2(wv, wv);
        }
        __syncthreads();

#pragma unroll
        for (int ci = 0; ci < 4; ++ci) {
            unsigned long long xp[9];
#pragma unroll
            for (int dy = 0; dy < 3; ++dy)
#pragma unroll
                for (int dx = 0; dx < 3; ++dx)
                    xp[dy * 3 + dx] = pack2(xt[ci][lr + dy][lc + dx],
                                            xt[ci][lr + 4 + dy][lc + dx]);
#pragma unroll
            for (int j = 0; j < 7; ++j) {
                int o = og * 7 + j;
                if (o < NOFF) {
#pragma unroll
                    for (int t = 0; t < 9; ++t)
                        ffma2(accp[j], xp[t], wdup[ci * 243 + o * 9 + t]);
                }
            }
        }
    }

    const int gy0 = by * 8 + lr;
    const int gx  = bx * 16 + lc;
#pragma unroll
    for (int j = 0; j < 7; ++j) {
        int o = og * 7 + j;
        if (o < NOFF) {
            float bb = __ldg(ob + o);
            float2 a = unpack2(accp[j]);
            g_om[((size_t)(b * NOFF + o) << 12) + (gy0 << 6) + gx]       = a.x + bb;
            g_om[((size_t)(b * NOFF + o) << 12) + ((gy0 + 4) << 6) + gx] = a.y + bb;
        }
    }
}

// ---------------------------------------------------------------------------
// Kernel B: deformable sampling (NHWC vector gathers) + mma.sync tf32 GEMM.
// Block tile = 64 px x 128 o, 2 blocks/SM. kt-major K, 36 chunks of 32,
// double-buffered, 1 sync/chunk. fillA: thread = (px, 8-ci group); 4 corners
// x 2 LDG.128 each -> 100% sector utilization.
// ---------------------------------------------------------------------------
__global__ __launch_bounds__(256, 2) void dcn_main_kernel(
    const float* __restrict__ bias) {
    extern __shared__ char smem[];
    const int tid  = threadIdx.x;
    const int wid  = tid >> 5;
    const int lane = tid & 31;
    const int wr   = wid >> 2;
    const int wc   = wid & 3;
    const int fr   = lane >> 2;
    const int fc   = lane & 3;

    const int m0      = blockIdx.x * 64;
    const int b       = m0 >> 12;
    const int rowbase = m0 & 4095;
    const int h0      = rowbase >> 6;

    float*   s_sum  = (float*)(smem + OFF_SUM);
    float*   s_ssq  = (float*)(smem + OFF_SSQ);
    float*   s_bias = (float*)(smem + OFF_BIAS);
    ushort4* s_co   = (ushort4*)(smem + OFF_CO);
    float4*  s_wq   = (float4*)(smem + OFF_WQ);
    uint32_t* s_Ab[2] = {(uint32_t*)(smem + OFF_A0), (uint32_t*)(smem + OFF_A1)};
    uint32_t* s_Wb[2] = {(uint32_t*)(smem + OFF_W0), (uint32_t*)(smem + OFF_W1)};

    if (tid < NC) {
        s_sum[tid] = 0.0f;
        s_ssq[tid] = 0.0f;
        s_bias[tid] = bias[tid];
    }

    // -------- phase 1: sampling metadata (9 taps x 64 px) --------
    for (int idx = tid; idx < NKT * 64; idx += 256) {
        int kt = idx >> 6;
        int px = idx & 63;
        int h  = h0;
        int w  = px;
        const float* omb = g_om + (size_t)b * NOFF * NHW;
        float offy = omb[(2 * kt) * NHW + (h << 6) + w];
        float offx = omb[(2 * kt + 1) * NHW + (h << 6) + w];
        float mv   = omb[(18 + kt) * NHW + (h << 6) + w];
        float msk  = 1.0f / (1.0f + expf(-mv));

        float py  = offy + (float)(h - 1 + kt / 3);
        float pxf = offx + (float)(w - 1 + kt % 3);
        float fy = floorf(py), fx = floorf(pxf);
        float ly = py - fy,    lx = pxf - fx;
        int y0 = (int)fy, x0 = (int)fx;
        int y1 = y0 + 1,  x1 = x0 + 1;
        float vy0 = (y0 >= 0 && y0 < NH) ? 1.0f : 0.0f;
        float vy1 = (y1 >= 0 && y1 < NH) ? 1.0f : 0.0f;
        float vx0 = (x0 >= 0 && x0 < NW) ? 1.0f : 0.0f;
        float vx1 = (x1 >= 0 && x1 < NW) ? 1.0f : 0.0f;

        float4 wq;
        wq.x = (1.0f - ly) * (1.0f - lx) * msk * vy0 * vx0;
        wq.y = (1.0f - ly) * lx          * msk * vy0 * vx1;
        wq.z = ly          * (1.0f - lx) * msk * vy1 * vx0;
        wq.w = ly          * lx          * msk * vy1 * vx1;
        s_wq[idx] = wq;

        int y0c = min(max(y0, 0), NH - 1), x0c = min(max(x0, 0), NW - 1);
        int y1c = min(max(y1, 0), NH - 1), x1c = min(max(x1, 0), NW - 1);
        ushort4 co;   // plane index y*64+x (<=4095)
        co.x = (unsigned short)((y0c << 6) + x0c);
        co.y = (unsigned short)((y0c << 6) + x1c);
        co.z = (unsigned short)((y1c << 6) + x0c);
        co.w = (unsigned short)((y1c << 6) + x1c);
        s_co[idx] = co;
    }

    float4 acc[2][4];
#pragma unroll
    for (int i = 0; i < 2; ++i)
#pragma unroll
        for (int j = 0; j < 4; ++j)
            acc[i][j] = make_float4(0.f, 0.f, 0.f, 0.f);

    const int cig = tid >> 6;      // 0..3: 8-channel group within the 32-chunk
    const int px  = tid & 63;

    // fillA: chunk c -> tap kt=c>>2, channels ci0=(c&3)*32. Thread covers
    // 8 channels [cig*8, cig*8+8) of pixel px via NHWC vector loads.
    auto fillA = [&](uint32_t* sA, int c) {
        const int kt   = c >> 2;
        const int cib  = ((c & 3) << 5) + (cig << 3);
        const int midx = (kt << 6) + px;
        const float4  wq = s_wq[midx];
        const ushort4 co = s_co[midx];
        const float* base = g_xT + ((size_t)b << 19) + cib;
        const float4* p0 = (const float4*)(base + ((int)co.x << 7));
        const float4* p1 = (const float4*)(base + ((int)co.y << 7));
        const float4* p2 = (const float4*)(base + ((int)co.z << 7));
        const float4* p3 = (const float4*)(base + ((int)co.w << 7));
        uint32_t* dst = sA + px * TSTRIDE + (cig << 3);
#pragma unroll
        for (int hf = 0; hf < 2; ++hf) {
            float4 a0 = __ldg(p0 + hf);
            float4 a1 = __ldg(p1 + hf);
            float4 a2 = __ldg(p2 + hf);
            float4 a3 = __ldg(p3 + hf);
            float v0 = wq.x * a0.x + wq.y * a1.x + wq.z * a2.x + wq.w * a3.x;
            float v1 = wq.x * a0.y + wq.y * a1.y + wq.z * a2.y + wq.w * a3.y;
            float v2 = wq.x * a0.z + wq.y * a1.z + wq.z * a2.z + wq.w * a3.z;
            float v3 = wq.x * a0.w + wq.y * a1.w + wq.z * a2.w + wq.w * a3.w;
            *(uint4*)(dst + hf * 4) =
                make_uint4(f2tf32(v0), f2tf32(v1), f2tf32(v2), f2tf32(v3));
        }
    };
    auto fillW = [&](uint32_t* sW, int c) {
        const uint32_t* wrow = g_w2 + c * 32 + lane;
#pragma unroll
        for (int r2 = 0; r2 < 16; ++r2) {
            int o = wid * 16 + r2;
            sW[o * TSTRIDE + lane] = __ldg(wrow + o * KDIM);
        }
    };

    __syncthreads();  // phase-1 metadata ready
    fillA(s_Ab[0], 0);
    fillW(s_Wb[0], 0);
    __syncthreads();

    // -------- phase 2: 36 K-chunks, double-buffered, 1 sync/chunk --------
    for (int c = 0; c < 36; ++c) {
        const int st = c & 1;
        if (c < 35) {
            fillA(s_Ab[st ^ 1], c + 1);
            fillW(s_Wb[st ^ 1], c + 1);
        }
        const uint32_t* s_A = s_Ab[st];
        const uint32_t* s_W = s_Wb[st];
#pragma unroll
        for (int ks = 0; ks < 4; ++ks) {
            const int kb = ks * 8;
            uint32_t bfr[4][2];
#pragma unroll
            for (int j = 0; j < 4; ++j) {
                const uint32_t* wp =
                    s_W + (wc * 32 + j * 8 + fr) * TSTRIDE + kb + fc;
                bfr[j][0] = wp[0];
                bfr[j][1] = wp[4];
            }
#pragma unroll
            for (int i = 0; i < 2; ++i) {
                uint32_t afr[4];
                const uint32_t* ap =
                    s_A + (wr * 32 + i * 16 + fr) * TSTRIDE + kb + fc;
                afr[0] = ap[0];
                afr[1] = ap[8 * TSTRIDE];
                afr[2] = ap[4];
                afr[3] = ap[8 * TSTRIDE + 4];
#pragma unroll
                for (int j = 0; j < 4; ++j)
                    mma_tf32(acc[i][j], afr, bfr[j]);
            }
        }
        __syncthreads();
    }

    // -------- epilogue: bias, store y, BN partial stats --------
#pragma unroll
    for (int j = 0; j < 4; ++j) {
#pragma unroll
        for (int t = 0; t < 2; ++t) {
            int o = wc * 32 + j * 8 + 2 * fc + t;
            float bo = s_bias[o];
            float* yp = g_y + (((size_t)((b << 7) + o)) << 12) + rowbase;
            float s = 0.0f, q = 0.0f;
#pragma unroll
            for (int i = 0; i < 2; ++i) {
                float v1 = (t ? acc[i][j].y : acc[i][j].x) + bo;
                float v2 = (t ? acc[i][j].w : acc[i][j].z) + bo;
                int p1 = wr * 32 + i * 16 + fr;
                yp[p1]     = v1;
                yp[p1 + 8] = v2;
                s += v1 + v2;
                q += v1 * v1 + v2 * v2;
            }
            atomicAdd(&s_sum[o], s);
            atomicAdd(&s_ssq[o], q);
        }
    }
    __syncthreads();
    if (tid < NC) {
        atomicAdd(&g_stats[tid],      s_sum[tid]);
        atomicAdd(&g_stats[NC + tid], s_ssq[tid]);
    }
}

// ---------------------------------------------------------------------------
// Kernel D: BatchNorm (batch stats) + ReLU -> d_out
// ---------------------------------------------------------------------------
__global__ __launch_bounds__(256) void bn_relu_kernel(
    float* __restrict__ out,
    const float* __restrict__ gamma,
    const float* __restrict__ beta) {
    int idx = blockIdx.x * 256 + threadIdx.x;
    int o = (idx >> 10) & 127;
    const float invN = 1.0f / 32768.0f;
    float mean = g_stats[o] * invN;
    float var  = g_stats[NC + o] * invN - mean * mean;
    float inv  = rsqrtf(var + 1e-5f);
    float sc   = gamma[o] * inv;
    float sh   = beta[o] - mean * sc;
    float4 v = ((const float4*)g_y)[idx];
    v.x = fmaxf(fmaf(v.x, sc, sh), 0.0f);
    v.y = fmaxf(fmaf(v.y, sc, sh), 0.0f);
    v.z = fmaxf(fmaf(v.z, sc, sh), 0.0f);
    v.w = fmaxf(fmaf(v.w, sc, sh), 0.0f);
    ((float4*)out)[idx] = v;
}

// ---------------------------------------------------------------------------
extern "C" void kernel_launch(void* const* d_in, const int* in_sizes, int n_in,
                              void* d_out, int out_size) {
    const float* x     = (const float*)d_in[0];
    const float* off_w = (const float*)d_in[1];
    const float* off_b = (const float*)d_in[2];
    const float* w     = (const float*)d_in[3];
    const float* bias  = (const float*)d_in[4];
    const float* gamma = (const float*)d_in[5];
    const float* beta  = (const float*)d_in[6];
    float* out = (float*)d_out;

    cudaFuncSetAttribute(dcn_main_kernel,
                         cudaFuncAttributeMaxDynamicSharedMemorySize, SMEM_SZ);

    prep_kernel<<<144, 256>>>(w);
    transpose_kernel<<<dim3(8, 64, 8), 256>>>(x);
    off_conv_kernel<<<dim3(4, 8, 8), 256>>>(x, off_w, off_b);
    dcn_main_kernel<<<512, 256, SMEM_SZ>>>(bias);
    bn_relu_kernel<<<4096, 256>>>(out, gamma, beta);
}

// round 12
// speedup vs baseline: 1.9445x; 1.9445x over previous
#include <cuda_runtime.h>
#include <cuda_bf16.h>
#include <math.h>
#include <stdint.h>

// Shapes: x[8,128,64,64] off_w[27,128,3,3] off_b[27] w[128,128,3,3] b[128]
//         gamma[128] beta[128] -> out[8,128,64,64] fp32

#define NB   8
#define NC   128
#define NH   64
#define NW   64
#define NHW  4096
#define NKT  9
#define NOFF 27
#define KDIM 1152   // 128*9

static __device__ float    g_om[NB * NOFF * NHW];  // offset-conv output
static __device__ uint32_t g_w2[NC * KDIM];        // main w [o][kt*128+ci], tf32 bits
static __device__ uint32_t g_ow2[32 * KDIM];       // off w  [o][kt*128+ci], tf32, rows 27..31 = 0
static __device__ float    g_y[NB * NC * NHW];     // pre-BN conv output
static __device__ float    g_stats[2 * NC];        // per-channel sum, sumsq

// ---------------- helpers ---------------------------------------------------
__device__ __forceinline__ uint32_t f2tf32(float v) {
    uint32_t r;
    asm("cvt.rna.tf32.f32 %0, %1;" : "=r"(r) : "f"(v));
    return r;
}
__device__ __forceinline__ void mma_tf32(float4& d, const uint32_t a[4],
                                         const uint32_t b[2]) {
    asm volatile(
        "mma.sync.aligned.m16n8k8.row.col.f32.tf32.tf32.f32 "
        "{%0,%1,%2,%3}, {%4,%5,%6,%7}, {%8,%9}, {%0,%1,%2,%3};"
        : "+f"(d.x), "+f"(d.y), "+f"(d.z), "+f"(d.w)
        : "r"(a[0]), "r"(a[1]), "r"(a[2]), "r"(a[3]), "r"(b[0]), "r"(b[1]));
}

// SMEM layout for dcn_main (dynamic, byte offsets). Tiles stride 36 floats.
#define OFF_SUM  0         // 512
#define OFF_SSQ  512       // 512
#define OFF_BIAS 1024      // 512
#define OFF_CO   1536      // 9*64*8  = 4608 (ushort4 corner byte-offsets)
#define OFF_WQ   6144      // 9*64*16 = 9216 (float4 bilinear weights)
#define OFF_A0   15360     // 64*36*4 = 9216
#define OFF_A1   24576
#define OFF_W0   33792     // 128*36*4 = 18432
#define OFF_W1   52224
#define SMEM_SZ  70656
#define TSTRIDE  36

// ---------------------------------------------------------------------------
// Kernel Z: zero stats + permute both weight tensors to kt-major tf32
// ---------------------------------------------------------------------------
__global__ void prep_kernel(const float* __restrict__ w,
                            const float* __restrict__ ow) {
    if (blockIdx.x == 0 && threadIdx.x < 2 * NC) g_stats[threadIdx.x] = 0.0f;
    int n = NC * KDIM;
    for (int i = blockIdx.x * blockDim.x + threadIdx.x; i < n;
         i += gridDim.x * blockDim.x) {
        int o  = i / KDIM;
        int r  = i - o * KDIM;
        int kt = r >> 7;
        int ci = r & 127;
        g_w2[i] = f2tf32(w[o * KDIM + ci * 9 + kt]);
    }
    int n2 = 32 * KDIM;
    for (int i = blockIdx.x * blockDim.x + threadIdx.x; i < n2;
         i += gridDim.x * blockDim.x) {
        int o  = i / KDIM;
        int r  = i - o * KDIM;
        int kt = r >> 7;
        int ci = r & 127;
        g_ow2[i] = (o < NOFF) ? f2tf32(ow[o * KDIM + ci * 9 + kt]) : 0u;
    }
}

// ---------------------------------------------------------------------------
// Kernel A: offset conv as tf32 mma GEMM.
// Block = 128 px (2 rows) x 32 o (27 real). K=1152 kt-major, 36 chunks of 32,
// double-buffered, 1 sync/chunk. A-fill is a coalesced bounds-masked LDG
// (regular 3x3 taps, no deformation). Warp tile 16px x 32o, acc 16 regs.
// ---------------------------------------------------------------------------
__global__ __launch_bounds__(256) void off_mma_kernel(
    const float* __restrict__ x,
    const float* __restrict__ ob) {
    __shared__ uint32_t sA[2][128 * TSTRIDE];
    __shared__ uint32_t sW[2][32 * TSTRIDE];
    __shared__ float    sb[32];

    const int tid  = threadIdx.x;
    const int wid  = tid >> 5;    // 0..7 -> M sixteenth
    const int lane = tid & 31;
    const int fr   = lane >> 2;
    const int fc   = lane & 3;

    const int m0      = blockIdx.x * 128;
    const int b       = m0 >> 12;
    const int rowbase = m0 & 4095;
    const int h0      = rowbase >> 6;

    if (tid < 32) sb[tid] = (tid < NOFF) ? __ldg(ob + tid) : 0.0f;

    const int px  = tid & 127;
    const int cig = tid >> 7;          // 0/1: 16-channel half of the chunk
    const int h   = h0 + (px >> 6);
    const int w   = px & 63;

    auto fillA = [&](uint32_t* A, int c) {
        const int kt  = c >> 2;
        const int ci0 = ((c & 3) << 5) + (cig << 4);
        const int y   = h - 1 + kt / 3;
        const int xx  = w - 1 + kt % 3;
        const bool valid = ((unsigned)y < NH) && ((unsigned)xx < NW);
        const float* p =
            x + (((size_t)((b << 7) + ci0)) << 12) + (y << 6) + xx;
        uint32_t* dst = A + px * TSTRIDE + (cig << 4);
        uint32_t pk[4];
#pragma unroll
        for (int j = 0; j < 16; ++j) {
            float v = valid ? __ldg(p + (j << 12)) : 0.0f;
            pk[j & 3] = f2tf32(v);
            if ((j & 3) == 3)
                *(uint4*)(dst + (j - 3)) = make_uint4(pk[0], pk[1], pk[2], pk[3]);
        }
    };
    auto fillW = [&](uint32_t* W, int c) {
        const uint32_t* wrow = g_ow2 + c * 32 + lane;
#pragma unroll
        for (int r2 = 0; r2 < 4; ++r2) {
            int o = wid * 4 + r2;
            W[o * TSTRIDE + lane] = __ldg(wrow + o * KDIM);
        }
    };

    float4 acc[4];
#pragma unroll
    for (int j = 0; j < 4; ++j) acc[j] = make_float4(0.f, 0.f, 0.f, 0.f);

    fillA(sA[0], 0);
    fillW(sW[0], 0);
    __syncthreads();

    for (int c = 0; c < 36; ++c) {
        const int st = c & 1;
        if (c < 35) {
            fillA(sA[st ^ 1], c + 1);
            fillW(sW[st ^ 1], c + 1);
        }
        const uint32_t* A = sA[st];
        const uint32_t* W = sW[st];
#pragma unroll
        for (int ks = 0; ks < 4; ++ks) {
            const int kb = ks * 8;
            uint32_t afr[4];
            const uint32_t* ap = A + (wid * 16 + fr) * TSTRIDE + kb + fc;
            afr[0] = ap[0];
            afr[1] = ap[8 * TSTRIDE];
            afr[2] = ap[4];
            afr[3] = ap[8 * TSTRIDE + 4];
#pragma unroll
            for (int j = 0; j < 4; ++j) {
                uint32_t bfr[2];
                const uint32_t* wp = W + (j * 8 + fr) * TSTRIDE + kb + fc;
                bfr[0] = wp[0];
                bfr[1] = wp[4];
                mma_tf32(acc[j], afr, bfr);
            }
        }
        __syncthreads();
    }

    // epilogue: om = acc + off_b  (rows 27..31 dropped)
#pragma unroll
    for (int j = 0; j < 4; ++j) {
#pragma unroll
        for (int t = 0; t < 2; ++t) {
            int o = j * 8 + 2 * fc + t;
            if (o < NOFF) {
                float bo = sb[o];
                float* yp = g_om + (((size_t)(b * NOFF + o)) << 12) + rowbase;
                int p1 = wid * 16 + fr;
                yp[p1]     = (t ? acc[j].y : acc[j].x) + bo;
                yp[p1 + 8] = (t ? acc[j].w : acc[j].z) + bo;
            }
        }
    }
}

// ---------------------------------------------------------------------------
// Kernel B: deformable sampling (NCHW coalesced gathers) + mma.sync tf32 GEMM.
// Block tile = 64 px x 128 o, 2 blocks/SM. kt-major K, 36 chunks of 32,
// double-buffered, 1 sync/chunk.  (R10 configuration — 344us baseline.)
// ---------------------------------------------------------------------------
__global__ __launch_bounds__(256, 2) void dcn_main_kernel(
    const float* __restrict__ x,
    const float* __restrict__ bias) {
    extern __shared__ char smem[];
    const int tid  = threadIdx.x;
    const int wid  = tid >> 5;
    const int lane = tid & 31;
    const int wr   = wid >> 2;
    const int wc   = wid & 3;
    const int fr   = lane >> 2;
    const int fc   = lane & 3;

    const int m0      = blockIdx.x * 64;
    const int b       = m0 >> 12;
    const int rowbase = m0 & 4095;
    const int h0      = rowbase >> 6;

    float*   s_sum  = (float*)(smem + OFF_SUM);
    float*   s_ssq  = (float*)(smem + OFF_SSQ);
    float*   s_bias = (float*)(smem + OFF_BIAS);
    ushort4* s_co   = (ushort4*)(smem + OFF_CO);
    float4*  s_wq   = (float4*)(smem + OFF_WQ);
    uint32_t* s_Ab[2] = {(uint32_t*)(smem + OFF_A0), (uint32_t*)(smem + OFF_A1)};
    uint32_t* s_Wb[2] = {(uint32_t*)(smem + OFF_W0), (uint32_t*)(smem + OFF_W1)};

    if (tid < NC) {
        s_sum[tid] = 0.0f;
        s_ssq[tid] = 0.0f;
        s_bias[tid] = bias[tid];
    }

    // -------- phase 1: sampling metadata (9 taps x 64 px) --------
    for (int idx = tid; idx < NKT * 64; idx += 256) {
        int kt = idx >> 6;
        int px = idx & 63;
        int h  = h0;
        int w  = px;
        const float* omb = g_om + (size_t)b * NOFF * NHW;
        float offy = omb[(2 * kt) * NHW + (h << 6) + w];
        float offx = omb[(2 * kt + 1) * NHW + (h << 6) + w];
        float mv   = omb[(18 + kt) * NHW + (h << 6) + w];
        float msk  = 1.0f / (1.0f + expf(-mv));

        float py  = offy + (float)(h - 1 + kt / 3);
        float pxf = offx + (float)(w - 1 + kt % 3);
        float fy = floorf(py), fx = floorf(pxf);
        float ly = py - fy,    lx = pxf - fx;
        int y0 = (int)fy, x0 = (int)fx;
        int y1 = y0 + 1,  x1 = x0 + 1;
        float vy0 = (y0 >= 0 && y0 < NH) ? 1.0f : 0.0f;
        float vy1 = (y1 >= 0 && y1 < NH) ? 1.0f : 0.0f;
        float vx0 = (x0 >= 0 && x0 < NW) ? 1.0f : 0.0f;
        float vx1 = (x1 >= 0 && x1 < NW) ? 1.0f : 0.0f;

        float4 wq;
        wq.x = (1.0f - ly) * (1.0f - lx) * msk * vy0 * vx0;
        wq.y = (1.0f - ly) * lx          * msk * vy0 * vx1;
        wq.z = ly          * (1.0f - lx) * msk * vy1 * vx0;
        wq.w = ly          * lx          * msk * vy1 * vx1;
        s_wq[idx] = wq;

        int y0c = min(max(y0, 0), NH - 1), x0c = min(max(x0, 0), NW - 1);
        int y1c = min(max(y1, 0), NH - 1), x1c = min(max(x1, 0), NW - 1);
        ushort4 co;  // byte offsets within a plane
        co.x = (unsigned short)(((y0c << 6) + x0c) << 2);
        co.y = (unsigned short)(((y0c << 6) + x1c) << 2);
        co.z = (unsigned short)(((y1c << 6) + x0c) << 2);
        co.w = (unsigned short)(((y1c << 6) + x1c) << 2);
        s_co[idx] = co;
    }

    float4 acc[2][4];
#pragma unroll
    for (int i = 0; i < 2; ++i)
#pragma unroll
        for (int j = 0; j < 4; ++j)
            acc[i][j] = make_float4(0.f, 0.f, 0.f, 0.f);

    const int cig = tid >> 6;      // 0..3: 8-channel group within the 32-chunk
    const int px  = tid & 63;

    auto fillA = [&](uint32_t* sA, int c) {
        const int kt   = c >> 2;
        const int cib  = ((c & 3) << 5) + (cig << 3);
        const int midx = (kt << 6) + px;
        const float4  wq = s_wq[midx];
        const ushort4 co = s_co[midx];
        const char* bpx = (const char*)x + (((size_t)((b << 7) + cib)) << 14);
        uint32_t* dst = sA + px * TSTRIDE + (cig << 3);
        uint32_t pk[4];
#pragma unroll
        for (int j = 0; j < 8; ++j) {
            const char* p = bpx + j * 16384;
            float v = wq.x * __ldg((const float*)(p + co.x))
                    + wq.y * __ldg((const float*)(p + co.y))
                    + wq.z * __ldg((const float*)(p + co.z))
                    + wq.w * __ldg((const float*)(p + co.w));
            pk[j & 3] = f2tf32(v);
            if ((j & 3) == 3)
                *(uint4*)(dst + (j - 3)) = make_uint4(pk[0], pk[1], pk[2], pk[3]);
        }
    };
    auto fillW = [&](uint32_t* sW, int c) {
        const uint32_t* wrow = g_w2 + c * 32 + lane;
#pragma unroll
        for (int r2 = 0; r2 < 16; ++r2) {
            int o = wid * 16 + r2;
            sW[o * TSTRIDE + lane] = __ldg(wrow + o * KDIM);
        }
    };

    __syncthreads();  // phase-1 metadata ready
    fillA(s_Ab[0], 0);
    fillW(s_Wb[0], 0);
    __syncthreads();

    // -------- phase 2: 36 K-chunks, double-buffered, 1 sync/chunk --------
    for (int c = 0; c < 36; ++c) {
        const int st = c & 1;
        if (c < 35) {
            fillA(s_Ab[st ^ 1], c + 1);
            fillW(s_Wb[st ^ 1], c + 1);
        }
        const uint32_t* s_A = s_Ab[st];
        const uint32_t* s_W = s_Wb[st];
#pragma unroll
        for (int ks = 0; ks < 4; ++ks) {
            const int kb = ks * 8;
            uint32_t bfr[4][2];
#pragma unroll
            for (int j = 0; j < 4; ++j) {
                const uint32_t* wp =
                    s_W + (wc * 32 + j * 8 + fr) * TSTRIDE + kb + fc;
                bfr[j][0] = wp[0];
                bfr[j][1] = wp[4];
            }
#pragma unroll
            for (int i = 0; i < 2; ++i) {
                uint32_t afr[4];
                const uint32_t* ap =
                    s_A + (wr * 32 + i * 16 + fr) * TSTRIDE + kb + fc;
                afr[0] = ap[0];
                afr[1] = ap[8 * TSTRIDE];
                afr[2] = ap[4];
                afr[3] = ap[8 * TSTRIDE + 4];
#pragma unroll
                for (int j = 0; j < 4; ++j)
                    mma_tf32(acc[i][j], afr, bfr[j]);
            }
        }
        __syncthreads();
    }

    // -------- epilogue: bias, store y, BN partial stats --------
#pragma unroll
    for (int j = 0; j < 4; ++j) {
#pragma unroll
        for (int t = 0; t < 2; ++t) {
            int o = wc * 32 + j * 8 + 2 * fc + t;
            float bo = s_bias[o];
            float* yp = g_y + (((size_t)((b << 7) + o)) << 12) + rowbase;
            float s = 0.0f, q = 0.0f;
#pragma unroll
            for (int i = 0; i < 2; ++i) {
                float v1 = (t ? acc[i][j].y : acc[i][j].x) + bo;
                float v2 = (t ? acc[i][j].w : acc[i][j].z) + bo;
                int p1 = wr * 32 + i * 16 + fr;
                yp[p1]     = v1;
                yp[p1 + 8] = v2;
                s += v1 + v2;
                q += v1 * v1 + v2 * v2;
            }
            atomicAdd(&s_sum[o], s);
            atomicAdd(&s_ssq[o], q);
        }
    }
    __syncthreads();
    if (tid < NC) {
        atomicAdd(&g_stats[tid],      s_sum[tid]);
        atomicAdd(&g_stats[NC + tid], s_ssq[tid]);
    }
}

// ---------------------------------------------------------------------------
// Kernel D: BatchNorm (batch stats) + ReLU -> d_out
// ---------------------------------------------------------------------------
__global__ __launch_bounds__(256) void bn_relu_kernel(
    float* __restrict__ out,
    const float* __restrict__ gamma,
    const float* __restrict__ beta) {
    int idx = blockIdx.x * 256 + threadIdx.x;
    int o = (idx >> 10) & 127;
    const float invN = 1.0f / 32768.0f;
    float mean = g_stats[o] * invN;
    float var  = g_stats[NC + o] * invN - mean * mean;
    float inv  = rsqrtf(var + 1e-5f);
    float sc   = gamma[o] * inv;
    float sh   = beta[o] - mean * sc;
    float4 v = ((const float4*)g_y)[idx];
    v.x = fmaxf(fmaf(v.x, sc, sh), 0.0f);
    v.y = fmaxf(fmaf(v.y, sc, sh), 0.0f);
    v.z = fmaxf(fmaf(v.z, sc, sh), 0.0f);
    v.w = fmaxf(fmaf(v.w, sc, sh), 0.0f);
    ((float4*)out)[idx] = v;
}

// ---------------------------------------------------------------------------
extern "C" void kernel_launch(void* const* d_in, const int* in_sizes, int n_in,
                              void* d_out, int out_size) {
    const float* x     = (const float*)d_in[0];
    const float* off_w = (const float*)d_in[1];
    const float* off_b = (const float*)d_in[2];
    const float* w     = (const float*)d_in[3];
    const float* bias  = (const float*)d_in[4];
    const float* gamma = (const float*)d_in[5];
    const float* beta  = (const float*)d_in[6];
    float* out = (float*)d_out;

    cudaFuncSetAttribute(dcn_main_kernel,
                         cudaFuncAttributeMaxDynamicSharedMemorySize, SMEM_SZ);

    prep_kernel<<<144, 256>>>(w, off_w);
    off_mma_kernel<<<256, 256>>>(x, off_b);
    dcn_main_kernel<<<512, 256, SMEM_SZ>>>(x, bias);
    bn_relu_kernel<<<4096, 256>>>(out, gamma, beta);
}

// round 13
// speedup vs baseline: 1.9699x; 1.0131x over previous
#include <cuda_runtime.h>
#include <cuda_bf16.h>
#include <math.h>
#include <stdint.h>

// Shapes: x[8,128,64,64] off_w[27,128,3,3] off_b[27] w[128,128,3,3] b[128]
//         gamma[128] beta[128] -> out[8,128,64,64] fp32

#define NB   8
#define NC   128
#define NH   64
#define NW   64
#define NHW  4096
#define NKT  9
#define NOFF 27
#define KDIM 1152   // 128*9

static __device__ float    g_om[NB * NOFF * NHW];  // offset-conv output
static __device__ uint32_t g_w2[NC * KDIM];        // main w [o][kt*128+ci], tf32 bits
static __device__ uint32_t g_ow2[32 * KDIM];       // off w  [o][kt*128+ci], tf32, rows 27..31 = 0
static __device__ float    g_y[NB * NC * NHW];     // pre-BN conv output
static __device__ float    g_stats[2 * NC];        // per-channel sum, sumsq

// ---------------- helpers ---------------------------------------------------
__device__ __forceinline__ uint32_t f2tf32(float v) {
    uint32_t r;
    asm("cvt.rna.tf32.f32 %0, %1;" : "=r"(r) : "f"(v));
    return r;
}
__device__ __forceinline__ void mma_tf32(float4& d, const uint32_t a[4],
                                         const uint32_t b[2]) {
    asm volatile(
        "mma.sync.aligned.m16n8k8.row.col.f32.tf32.tf32.f32 "
        "{%0,%1,%2,%3}, {%4,%5,%6,%7}, {%8,%9}, {%0,%1,%2,%3};"
        : "+f"(d.x), "+f"(d.y), "+f"(d.z), "+f"(d.w)
        : "r"(a[0]), "r"(a[1]), "r"(a[2]), "r"(a[3]), "r"(b[0]), "r"(b[1]));
}

// SMEM layout for dcn_main (dynamic, byte offsets). Tiles stride 36 floats.
#define OFF_SUM  0         // 512
#define OFF_SSQ  512       // 512
#define OFF_BIAS 1024      // 512
#define OFF_CO   1536      // 9*64*8  = 4608 (ushort4 corner byte-offsets)
#define OFF_WQ   6144      // 9*64*16 = 9216 (float4 bilinear weights)
#define OFF_A0   15360     // 64*36*4 = 9216
#define OFF_A1   24576
#define OFF_W0   33792     // 128*36*4 = 18432
#define OFF_W1   52224
#define SMEM_SZ  70656
#define TSTRIDE  36

// ---------------------------------------------------------------------------
// Kernel Z: zero stats + permute both weight tensors to kt-major tf32
// ---------------------------------------------------------------------------
__global__ void prep_kernel(const float* __restrict__ w,
                            const float* __restrict__ ow) {
    if (blockIdx.x == 0 && threadIdx.x < 2 * NC) g_stats[threadIdx.x] = 0.0f;
    int n = NC * KDIM;
    for (int i = blockIdx.x * blockDim.x + threadIdx.x; i < n;
         i += gridDim.x * blockDim.x) {
        int o  = i / KDIM;
        int r  = i - o * KDIM;
        int kt = r >> 7;
        int ci = r & 127;
        g_w2[i] = f2tf32(w[o * KDIM + ci * 9 + kt]);
    }
    int n2 = 32 * KDIM;
    for (int i = blockIdx.x * blockDim.x + threadIdx.x; i < n2;
         i += gridDim.x * blockDim.x) {
        int o  = i / KDIM;
        int r  = i - o * KDIM;
        int kt = r >> 7;
        int ci = r & 127;
        g_ow2[i] = (o < NOFF) ? f2tf32(ow[o * KDIM + ci * 9 + kt]) : 0u;
    }
}

// ---------------------------------------------------------------------------
// Kernel A: offset conv as tf32 mma GEMM (LDG-stage -> gemm -> STS ordering).
// Block = 128 px x 32 o (27 real). K=1152 kt-major, 36 chunks of 32.
// ---------------------------------------------------------------------------
__global__ __launch_bounds__(256) void off_mma_kernel(
    const float* __restrict__ x,
    const float* __restrict__ ob) {
    __shared__ uint32_t sA[2][128 * TSTRIDE];
    __shared__ uint32_t sW[2][32 * TSTRIDE];
    __shared__ float    sb[32];

    const int tid  = threadIdx.x;
    const int wid  = tid >> 5;
    const int lane = tid & 31;
    const int fr   = lane >> 2;
    const int fc   = lane & 3;

    const int m0      = blockIdx.x * 128;
    const int b       = m0 >> 12;
    const int rowbase = m0 & 4095;
    const int h0      = rowbase >> 6;

    if (tid < 32) sb[tid] = (tid < NOFF) ? __ldg(ob + tid) : 0.0f;

    const int px  = tid & 127;
    const int cig = tid >> 7;          // 0/1: 16-channel half of the chunk
    const int h   = h0 + (px >> 6);
    const int w   = px & 63;

    auto loadA = [&](float* rg, int c) {
        const int kt  = c >> 2;
        const int ci0 = ((c & 3) << 5) + (cig << 4);
        const int y   = h - 1 + kt / 3;
        const int xx  = w - 1 + kt % 3;
        const bool valid = ((unsigned)y < NH) && ((unsigned)xx < NW);
        const float* p =
            x + (((size_t)((b << 7) + ci0)) << 12) + (y << 6) + xx;
#pragma unroll
        for (int j = 0; j < 16; ++j)
            rg[j] = valid ? __ldg(p + (j << 12)) : 0.0f;
    };
    auto storeA = [&](uint32_t* A, const float* rg) {
        uint32_t* dst = A + px * TSTRIDE + (cig << 4);
        uint32_t pk[4];
#pragma unroll
        for (int j = 0; j < 16; ++j) {
            pk[j & 3] = f2tf32(rg[j]);
            if ((j & 3) == 3)
                *(uint4*)(dst + (j - 3)) = make_uint4(pk[0], pk[1], pk[2], pk[3]);
        }
    };
    auto fillW = [&](uint32_t* W, int c) {
        const uint32_t* wrow = g_ow2 + c * 32 + lane;
#pragma unroll
        for (int r2 = 0; r2 < 4; ++r2) {
            int o = wid * 4 + r2;
            W[o * TSTRIDE + lane] = __ldg(wrow + o * KDIM);
        }
    };

    float4 acc[4];
#pragma unroll
    for (int j = 0; j < 4; ++j) acc[j] = make_float4(0.f, 0.f, 0.f, 0.f);

    float rg[16];
    loadA(rg, 0);
    storeA(sA[0], rg);
    fillW(sW[0], 0);
    __syncthreads();

    for (int c = 0; c < 36; ++c) {
        const int st = c & 1;
        if (c < 35) loadA(rg, c + 1);      // issue gathers, no consumer yet
        const uint32_t* A = sA[st];
        const uint32_t* W = sW[st];
#pragma unroll
        for (int ks = 0; ks < 4; ++ks) {
            const int kb = ks * 8;
            uint32_t afr[4];
            const uint32_t* ap = A + (wid * 16 + fr) * TSTRIDE + kb + fc;
            afr[0] = ap[0];
            afr[1] = ap[8 * TSTRIDE];
            afr[2] = ap[4];
            afr[3] = ap[8 * TSTRIDE + 4];
#pragma unroll
            for (int j = 0; j < 4; ++j) {
                uint32_t bfr[2];
                const uint32_t* wp = W + (j * 8 + fr) * TSTRIDE + kb + fc;
                bfr[0] = wp[0];
                bfr[1] = wp[4];
                mma_tf32(acc[j], afr, bfr);
            }
        }
        if (c < 35) {                      // now consume loads + refill W
            storeA(sA[st ^ 1], rg);
            fillW(sW[st ^ 1], c + 1);
        }
        __syncthreads();
    }

    // epilogue: om = acc + off_b  (rows 27..31 dropped)
#pragma unroll
    for (int j = 0; j < 4; ++j) {
#pragma unroll
        for (int t = 0; t < 2; ++t) {
            int o = j * 8 + 2 * fc + t;
            if (o < NOFF) {
                float bo = sb[o];
                float* yp = g_om + (((size_t)(b * NOFF + o)) << 12) + rowbase;
                int p1 = wid * 16 + fr;
                yp[p1]     = (t ? acc[j].y : acc[j].x) + bo;
                yp[p1 + 8] = (t ? acc[j].w : acc[j].z) + bo;
            }
        }
    }
}

// ---------------------------------------------------------------------------
// Kernel B: deformable sampling + mma.sync tf32 GEMM + BN stats.
// Block tile = 64 px x 128 o, 2 blocks/SM, kt-major K, 36 chunks.
// Per chunk: LDG-stage(c+1) -> gemm(c) -> combine+STS(c+1) -> fillW -> sync,
// so the L1tex queue drain overlaps gemm issue instead of stalling at STS.
// ---------------------------------------------------------------------------
__global__ __launch_bounds__(256, 2) void dcn_main_kernel(
    const float* __restrict__ x,
    const float* __restrict__ bias) {
    extern __shared__ char smem[];
    const int tid  = threadIdx.x;
    const int wid  = tid >> 5;
    const int lane = tid & 31;
    const int wr   = wid >> 2;
    const int wc   = wid & 3;
    const int fr   = lane >> 2;
    const int fc   = lane & 3;

    const int m0      = blockIdx.x * 64;
    const int b       = m0 >> 12;
    const int rowbase = m0 & 4095;
    const int h0      = rowbase >> 6;

    float*   s_sum  = (float*)(smem + OFF_SUM);
    float*   s_ssq  = (float*)(smem + OFF_SSQ);
    float*   s_bias = (float*)(smem + OFF_BIAS);
    ushort4* s_co   = (ushort4*)(smem + OFF_CO);
    float4*  s_wq   = (float4*)(smem + OFF_WQ);
    uint32_t* s_Ab[2] = {(uint32_t*)(smem + OFF_A0), (uint32_t*)(smem + OFF_A1)};
    uint32_t* s_Wb[2] = {(uint32_t*)(smem + OFF_W0), (uint32_t*)(smem + OFF_W1)};

    if (tid < NC) {
        s_sum[tid] = 0.0f;
        s_ssq[tid] = 0.0f;
        s_bias[tid] = bias[tid];
    }

    // -------- phase 1: sampling metadata (9 taps x 64 px) --------
    for (int idx = tid; idx < NKT * 64; idx += 256) {
        int kt = idx >> 6;
        int px = idx & 63;
        int h  = h0;
        int w  = px;
        const float* omb = g_om + (size_t)b * NOFF * NHW;
        float offy = omb[(2 * kt) * NHW + (h << 6) + w];
        float offx = omb[(2 * kt + 1) * NHW + (h << 6) + w];
        float mv   = omb[(18 + kt) * NHW + (h << 6) + w];
        float msk  = 1.0f / (1.0f + expf(-mv));

        float py  = offy + (float)(h - 1 + kt / 3);
        float pxf = offx + (float)(w - 1 + kt % 3);
        float fy = floorf(py), fx = floorf(pxf);
        float ly = py - fy,    lx = pxf - fx;
        int y0 = (int)fy, x0 = (int)fx;
        int y1 = y0 + 1,  x1 = x0 + 1;
        float vy0 = (y0 >= 0 && y0 < NH) ? 1.0f : 0.0f;
        float vy1 = (y1 >= 0 && y1 < NH) ? 1.0f : 0.0f;
        float vx0 = (x0 >= 0 && x0 < NW) ? 1.0f : 0.0f;
        float vx1 = (x1 >= 0 && x1 < NW) ? 1.0f : 0.0f;

        float4 wq;
        wq.x = (1.0f - ly) * (1.0f - lx) * msk * vy0 * vx0;
        wq.y = (1.0f - ly) * lx          * msk * vy0 * vx1;
        wq.z = ly          * (1.0f - lx) * msk * vy1 * vx0;
        wq.w = ly          * lx          * msk * vy1 * vx1;
        s_wq[idx] = wq;

        int y0c = min(max(y0, 0), NH - 1), x0c = min(max(x0, 0), NW - 1);
        int y1c = min(max(y1, 0), NH - 1), x1c = min(max(x1, 0), NW - 1);
        ushort4 co;  // byte offsets within a plane
        co.x = (unsigned short)(((y0c << 6) + x0c) << 2);
        co.y = (unsigned short)(((y0c << 6) + x1c) << 2);
        co.z = (unsigned short)(((y1c << 6) + x0c) << 2);
        co.w = (unsigned short)(((y1c << 6) + x1c) << 2);
        s_co[idx] = co;
    }

    float4 acc[2][4];
#pragma unroll
    for (int i = 0; i < 2; ++i)
#pragma unroll
        for (int j = 0; j < 4; ++j)
            acc[i][j] = make_float4(0.f, 0.f, 0.f, 0.f);

    const int cig = tid >> 6;      // 0..3: 8-channel group within the 32-chunk
    const int px  = tid & 63;

    auto loadA = [&](float* rg, int c) {
        const int kt   = c >> 2;
        const int cib  = ((c & 3) << 5) + (cig << 3);
        const int midx = (kt << 6) + px;
        const ushort4 co = s_co[midx];
        const char* bpx = (const char*)x + (((size_t)((b << 7) + cib)) << 14);
#pragma unroll
        for (int j = 0; j < 8; ++j) {
            const char* p = bpx + j * 16384;
            rg[4 * j + 0] = __ldg((const float*)(p + co.x));
            rg[4 * j + 1] = __ldg((const float*)(p + co.y));
            rg[4 * j + 2] = __ldg((const float*)(p + co.z));
            rg[4 * j + 3] = __ldg((const float*)(p + co.w));
        }
    };
    auto storeA = [&](uint32_t* sA, const float* rg, int c) {
        const int kt   = c >> 2;
        const int midx = (kt << 6) + px;
        const float4 wq = s_wq[midx];
        uint32_t* dst = sA + px * TSTRIDE + (cig << 3);
        uint32_t pk[4];
#pragma unroll
        for (int j = 0; j < 8; ++j) {
            float v = wq.x * rg[4 * j] + wq.y * rg[4 * j + 1] +
                      wq.z * rg[4 * j + 2] + wq.w * rg[4 * j + 3];
            pk[j & 3] = f2tf32(v);
            if ((j & 3) == 3)
                *(uint4*)(dst + (j - 3)) = make_uint4(pk[0], pk[1], pk[2], pk[3]);
        }
    };
    auto fillW = [&](uint32_t* sW, int c) {
        const uint32_t* wrow = g_w2 + c * 32 + lane;
#pragma unroll
        for (int r2 = 0; r2 < 16; ++r2) {
            int o = wid * 16 + r2;
            sW[o * TSTRIDE + lane] = __ldg(wrow + o * KDIM);
        }
    };

    __syncthreads();  // phase-1 metadata ready
    float rg[32];
    loadA(rg, 0);
    storeA(s_Ab[0], rg, 0);
    fillW(s_Wb[0], 0);
    __syncthreads();

    // -------- phase 2: 36 K-chunks, stage -> gemm -> store, 1 sync/chunk ----
    for (int c = 0; c < 36; ++c) {
        const int st = c & 1;
        if (c < 35) loadA(rg, c + 1);      // issue gathers; drain overlaps gemm
        const uint32_t* s_A = s_Ab[st];
        const uint32_t* s_W = s_Wb[st];
#pragma unroll
        for (int ks = 0; ks < 4; ++ks) {
            const int kb = ks * 8;
            uint32_t bfr[4][2];
#pragma unroll
            for (int j = 0; j < 4; ++j) {
                const uint32_t* wp =
                    s_W + (wc * 32 + j * 8 + fr) * TSTRIDE + kb + fc;
                bfr[j][0] = wp[0];
                bfr[j][1] = wp[4];
            }
#pragma unroll
            for (int i = 0; i < 2; ++i) {
                uint32_t afr[4];
                const uint32_t* ap =
                    s_A + (wr * 32 + i * 16 + fr) * TSTRIDE + kb + fc;
                afr[0] = ap[0];
                afr[1] = ap[8 * TSTRIDE];
                afr[2] = ap[4];
                afr[3] = ap[8 * TSTRIDE + 4];
#pragma unroll
                for (int j = 0; j < 4; ++j)
                    mma_tf32(acc[i][j], afr, bfr[j]);
            }
        }
        if (c < 35) {                      // consume staged loads
            storeA(s_Ab[st ^ 1], rg, c + 1);
            fillW(s_Wb[st ^ 1], c + 1);
        }
        __syncthreads();
    }

    // -------- epilogue: bias, store y, BN partial stats --------
#pragma unroll
    for (int j = 0; j < 4; ++j) {
#pragma unroll
        for (int t = 0; t < 2; ++t) {
            int o = wc * 32 + j * 8 + 2 * fc + t;
            float bo = s_bias[o];
            float* yp = g_y + (((size_t)((b << 7) + o)) << 12) + rowbase;
            float s = 0.0f, q = 0.0f;
#pragma unroll
            for (int i = 0; i < 2; ++i) {
                float v1 = (t ? acc[i][j].y : acc[i][j].x) + bo;
                float v2 = (t ? acc[i][j].w : acc[i][j].z) + bo;
                int p1 = wr * 32 + i * 16 + fr;
                yp[p1]     = v1;
                yp[p1 + 8] = v2;
                s += v1 + v2;
                q += v1 * v1 + v2 * v2;
            }
            atomicAdd(&s_sum[o], s);
            atomicAdd(&s_ssq[o], q);
        }
    }
    __syncthreads();
    if (tid < NC) {
        atomicAdd(&g_stats[tid],      s_sum[tid]);
        atomicAdd(&g_stats[NC + tid], s_ssq[tid]);
    }
}

// ---------------------------------------------------------------------------
// Kernel D: BatchNorm (batch stats) + ReLU -> d_out
// ---------------------------------------------------------------------------
__global__ __launch_bounds__(256) void bn_relu_kernel(
    float* __restrict__ out,
    const float* __restrict__ gamma,
    const float* __restrict__ beta) {
    int idx = blockIdx.x * 256 + threadIdx.x;
    int o = (idx >> 10) & 127;
    const float invN = 1.0f / 32768.0f;
    float mean = g_stats[o] * invN;
    float var  = g_stats[NC + o] * invN - mean * mean;
    float inv  = rsqrtf(var + 1e-5f);
    float sc   = gamma[o] * inv;
    float sh   = beta[o] - mean * sc;
    float4 v = ((const float4*)g_y)[idx];
    v.x = fmaxf(fmaf(v.x, sc, sh), 0.0f);
    v.y = fmaxf(fmaf(v.y, sc, sh), 0.0f);
    v.z = fmaxf(fmaf(v.z, sc, sh), 0.0f);
    v.w = fmaxf(fmaf(v.w, sc, sh), 0.0f);
    ((float4*)out)[idx] = v;
}

// ---------------------------------------------------------------------------
extern "C" void kernel_launch(void* const* d_in, const int* in_sizes, int n_in,
                              void* d_out, int out_size) {
    const float* x     = (const float*)d_in[0];
    const float* off_w = (const float*)d_in[1];
    const float* off_b = (const float*)d_in[2];
    const float* w     = (const float*)d_in[3];
    const float* bias  = (const float*)d_in[4];
    const float* gamma = (const float*)d_in[5];
    const float* beta  = (const float*)d_in[6];
    float* out = (float*)d_out;

    cudaFuncSetAttribute(dcn_main_kernel,
                         cudaFuncAttributeMaxDynamicSharedMemorySize, SMEM_SZ);

    prep_kernel<<<144, 256>>>(w, off_w);
    off_mma_kernel<<<256, 256>>>(x, off_b);
    dcn_main_kernel<<<512, 256, SMEM_SZ>>>(x, bias);
    bn_relu_kernel<<<4096, 256>>>(out, gamma, beta);
}